// round 6
// baseline (speedup 1.0000x reference)
#include <cuda_runtime.h>
#include <cstdint>

// 26 node coordinates (compile-time __constant__ init; no runtime copy)
__constant__ float2 c_nodes[26] = {
    {0.5454545454545454f, 0.76f}, {0.6022727272727273f, 0.76f},
    {0.5454545454545454f, 0.86f}, {0.6022727272727273f, 0.86f},
    {0.4772727272727273f, 0.76f}, {0.42045454545454547f, 0.76f},
    {0.42045454545454547f, 0.86f}, {0.4772727272727273f, 0.86f},
    {0.32954545454545453f, 0.808f}, {0.42045454545454547f, 0.48f},
    {0.4772727272727273f, 0.48f}, {0.4772727272727273f, 0.38f},
    {0.42045454545454547f, 0.38f}, {0.32954545454545453f, 0.428f},
    {0.5727272727272728f, 0.62f}, {0.7613636363636364f, 0.76f},
    {0.8181818181818182f, 0.76f}, {0.8181818181818182f, 0.86f},
    {0.7613636363636364f, 0.86f}, {0.7909090909090909f, 0.62f},
    {0.9431818181818182f, 0.76f}, {1.0f, 0.76f},
    {1.0f, 0.86f}, {0.9431818181818182f, 0.86f},
    {0.9727272727272728f, 0.62f}, {0.9727272727272728f, 1.0f}
};

// Output row = 272 floats = 68 float4 (f = 4c):
//   c in [2,32]  : emb1 floats [4c-6 .. 4c-3]  = e1 float2 idx {2c-3, 2c-2} (8B-aligned)
//   c in [35,65] : emb2 floats [4c-138..4c-135] = e2 float2 idx {2c-69, 2c-68}
//   c in {0,1,33,34,66,67} : boundary, scalar gather (smem x + emb edges)

constexpr int ROWS_PER_BLOCK = 64;   // 64 rows * 16 floats = 4KB smem
constexpr int THREADS = 256;         // 8 warps; 8 rows per warp

__global__ __launch_bounds__(THREADS) void pe_kernel(
    const float* __restrict__ x,
    const float* __restrict__ emb,
    float* __restrict__ out,
    int rows)
{
    __shared__ float4 s4[ROWS_PER_BLOCK * 16 / 4];   // staged x (4KB)
    __shared__ int2 s_eoff[ROWS_PER_BLOCK];          // per-row emb float2 base offsets

    int block_row0 = blockIdx.x * ROWS_PER_BLOCK;    // grid sized exactly

    // ── Phase 0: stage x (one coalesced float4 per thread, high MLP, paid once)
    {
        size_t fidx = (size_t)block_row0 * 4 + threadIdx.x;
        s4[threadIdx.x] = reinterpret_cast<const float4*>(x)[fidx];
    }
    __syncthreads();

    const float* sxf = reinterpret_cast<const float*>(s4);
    const float2* sx2 = reinterpret_cast<const float2*>(s4);

    int warp = threadIdx.x >> 5;
    int lane = threadIdx.x & 31;

    // ── Phase 1: ballots for 8 rows per warp -> emb row float2-offsets in smem
    {
        bool active = lane < 26;
        float nx = 0.f, ny = 0.f, tx = -1.f, ty = -1.f;
        if (active) {
            float2 n = c_nodes[lane];
            nx = n.x; ny = n.y;
            tx = 0.01f + 1e-5f * fabsf(nx);
            ty = 0.01f + 1e-5f * fabsf(ny);
        }
        #pragma unroll
        for (int r8 = 0; r8 < 8; r8++) {
            int r = warp * 8 + r8;
            float2 pt1 = sx2[r * 8 + 2];   // floats 4,5
            float2 pt2 = sx2[r * 8 + 4];   // floats 8,9
            bool m1 = active && (fabsf(pt1.x - nx) <= tx) && (fabsf(pt1.y - ny) <= ty);
            bool m2 = active && (fabsf(pt2.x - nx) <= tx) && (fabsf(pt2.y - ny) <= ty);
            int idx1 = __ffs(__ballot_sync(0xffffffffu, m1));  // 1-based == argmax+1
            int idx2 = __ffs(__ballot_sync(0xffffffffu, m2));
            if (lane == 0) s_eoff[r] = make_int2(idx1 * 64, idx2 * 64);  // float2 units
        }
    }
    __syncthreads();

    const float2* emb2 = reinterpret_cast<const float2*>(emb);

    // ── Phase 2: per row, 68 STG.128 (half the store-issue cost of STG.64);
    //    interior float4s = two aligned LDG.64 L1-hits; x pieces from smem.
    #pragma unroll 2
    for (int r8 = 0; r8 < 8; r8++) {
        int r = warp * 8 + r8;
        int grow = block_row0 + r;
        int2 eo = s_eoff[r];
        const float* xr = sxf + r * 16;
        float4* o4 = reinterpret_cast<float4*>(out + (size_t)grow * 272);

        #pragma unroll
        for (int i = 0; i < 3; i++) {
            int c = lane + i * 32;
            if (i < 2 || c < 68) {
                float4 v;
                if (c >= 2 && c <= 32) {
                    float2 a = emb2[eo.x + 2 * c - 3];
                    float2 b = emb2[eo.x + 2 * c - 2];
                    v = make_float4(a.x, a.y, b.x, b.y);
                } else if (c >= 35 && c <= 65) {
                    float2 a = emb2[eo.y + 2 * c - 69];
                    float2 b = emb2[eo.y + 2 * c - 68];
                    v = make_float4(a.x, a.y, b.x, b.y);
                } else {
                    const float* ef = reinterpret_cast<const float*>(emb2);
                    #pragma unroll
                    for (int j = 0; j < 4; j++) {
                        int f = 4 * c + j;
                        float s;
                        if (f < 6)        s = xr[f];                       // smem
                        else if (f < 134) s = ef[eo.x * 2 + f - 6];        // L1 hit
                        else if (f < 138) s = xr[f - 128];                 // smem
                        else if (f < 266) s = ef[eo.y * 2 + f - 138];      // L1 hit
                        else              s = xr[f - 256];                 // smem
                        (&v.x)[j] = s;
                    }
                }
                o4[c] = v;   // aligned STG.128
            }
        }
    }
}

extern "C" void kernel_launch(void* const* d_in, const int* in_sizes, int n_in,
                              void* d_out, int out_size)
{
    const float* x;
    const float* emb;
    int xsz;
    if (in_sizes[0] > in_sizes[1]) {
        x = (const float*)d_in[0]; emb = (const float*)d_in[1]; xsz = in_sizes[0];
    } else {
        x = (const float*)d_in[1]; emb = (const float*)d_in[0]; xsz = in_sizes[1];
    }
    int rows = xsz / 16;                                       // 262144
    int blocks = (rows + ROWS_PER_BLOCK - 1) / ROWS_PER_BLOCK; // 4096 (exact)
    pe_kernel<<<blocks, THREADS>>>(x, emb, (float*)d_out, rows);
}

// round 7
// speedup vs baseline: 1.4045x; 1.4045x over previous
#include <cuda_runtime.h>
#include <cstdint>

// 26 node coordinates (compile-time __constant__ init; no runtime copy)
__constant__ float2 c_nodes[26] = {
    {0.5454545454545454f, 0.76f}, {0.6022727272727273f, 0.76f},
    {0.5454545454545454f, 0.86f}, {0.6022727272727273f, 0.86f},
    {0.4772727272727273f, 0.76f}, {0.42045454545454547f, 0.76f},
    {0.42045454545454547f, 0.86f}, {0.4772727272727273f, 0.86f},
    {0.32954545454545453f, 0.808f}, {0.42045454545454547f, 0.48f},
    {0.4772727272727273f, 0.48f}, {0.4772727272727273f, 0.38f},
    {0.42045454545454547f, 0.38f}, {0.32954545454545453f, 0.428f},
    {0.5727272727272728f, 0.62f}, {0.7613636363636364f, 0.76f},
    {0.8181818181818182f, 0.76f}, {0.8181818181818182f, 0.86f},
    {0.7613636363636364f, 0.86f}, {0.7909090909090909f, 0.62f},
    {0.9431818181818182f, 0.76f}, {1.0f, 0.76f},
    {1.0f, 0.86f}, {0.9431818181818182f, 0.86f},
    {0.9727272727272728f, 0.62f}, {0.9727272727272728f, 1.0f}
};

// Output row = 272 floats = 136 float2:
//   c in [0,3)    -> x2[c]
//   c in [3,67)   -> e1[c-3]
//   c in [67,69)  -> x2[c-64]
//   c in [69,133) -> e2[c-69]
//   c in [133,136)-> x2[c-128]

constexpr int ROWS_PER_BLOCK = 128;   // 128 rows * 16 floats = 8KB smem
constexpr int THREADS = 512;          // 16 warps; 8 rows per warp

__global__ __launch_bounds__(THREADS) void pe_kernel(
    const float* __restrict__ x,
    const float* __restrict__ emb,
    float* __restrict__ out,
    int rows)
{
    __shared__ float4 s4[ROWS_PER_BLOCK * 16 / 4];   // staged x (8KB)

    int block_row0 = blockIdx.x * ROWS_PER_BLOCK;    // grid sized exactly

    // ── Phase 0: stage x (one coalesced float4 per thread, high MLP, paid once)
    {
        size_t fidx = (size_t)block_row0 * 4 + threadIdx.x;
        s4[threadIdx.x] = reinterpret_cast<const float4*>(x)[fidx];
    }
    __syncthreads();
    const float2* sx2 = reinterpret_cast<const float2*>(s4);

    int warp = threadIdx.x >> 5;
    int lane = threadIdx.x & 31;

    // Per-lane node + tolerance (lanes 0..25 active)
    bool active = lane < 26;
    float nx = 0.f, ny = 0.f, tx = -1.f, ty = -1.f;
    if (active) {
        float2 n = c_nodes[lane];
        nx = n.x; ny = n.y;
        tx = 0.01f + 1e-5f * fabsf(nx);
        ty = 0.01f + 1e-5f * fabsf(ny);
    }

    const float2* emb2 = reinterpret_cast<const float2*>(emb);

    #pragma unroll
    for (int r8 = 0; r8 < 8; r8++) {
        int r = warp * 8 + r8;                 // row within block
        int grow = block_row0 + r;

        float2 pt1 = sx2[r * 8 + 2];           // floats 4,5 (LDS)
        float2 pt2 = sx2[r * 8 + 4];           // floats 8,9

        bool m1 = active && (fabsf(pt1.x - nx) <= tx) && (fabsf(pt1.y - ny) <= ty);
        bool m2 = active && (fabsf(pt2.x - nx) <= tx) && (fabsf(pt2.y - ny) <= ty);
        int idx1 = __ffs(__ballot_sync(0xffffffffu, m1));  // 1-based == argmax+1
        int idx2 = __ffs(__ballot_sync(0xffffffffu, m2));

        const float2* e1 = emb2 + (size_t)idx1 * 64;
        const float2* e2 = emb2 + (size_t)idx2 * 64;
        const float2* x2 = sx2 + r * 8;
        float2* o = reinterpret_cast<float2*>(out + (size_t)grow * 272);

        #pragma unroll
        for (int i = 0; i < 5; i++) {
            int c = lane + i * 32;
            if (i < 4 || c < 136) {
                float2 v;
                if (c < 3)        v = x2[c];          // smem
                else if (c < 67)  v = e1[c - 3];      // L1-resident, dense 256B/warp
                else if (c < 69)  v = x2[c - 64];
                else if (c < 133) v = e2[c - 69];
                else              v = x2[c - 128];
                __stcs(&o[c], v);                      // streaming STG.64 (evict-first)
            }
        }
    }
}

extern "C" void kernel_launch(void* const* d_in, const int* in_sizes, int n_in,
                              void* d_out, int out_size)
{
    const float* x;
    const float* emb;
    int xsz;
    if (in_sizes[0] > in_sizes[1]) {
        x = (const float*)d_in[0]; emb = (const float*)d_in[1]; xsz = in_sizes[0];
    } else {
        x = (const float*)d_in[1]; emb = (const float*)d_in[0]; xsz = in_sizes[1];
    }
    int rows = xsz / 16;                                       // 262144
    int blocks = (rows + ROWS_PER_BLOCK - 1) / ROWS_PER_BLOCK; // 2048 (exact)
    pe_kernel<<<blocks, THREADS>>>(x, emb, (float*)d_out, rows);
}